// round 1
// baseline (speedup 1.0000x reference)
#include <cuda_runtime.h>
#include <math.h>

// Problem dims
#define BATCH 512
#define TSTEPS 32
#define BELIEF 1024
#define STATE 256
#define HIDDEN 1024
#define EMB 1024

// ---------------- scratch (device globals; no allocations) ----------------
__device__ float g_hidden[BATCH * BELIEF];     // relu embed state
__device__ float g_gi[BATCH * 3 * BELIEF];     // GRU input gates
__device__ float g_gh[BATCH * 3 * BELIEF];     // GRU hidden gates
__device__ float g_hp[BATCH * HIDDEN];         // posterior hidden
__device__ float g_hq[BATCH * HIDDEN];         // prior hidden
__device__ float g_ypo[BATCH * 2 * STATE];     // posterior head raw
__device__ float g_ypr[BATCH * 2 * STATE];     // prior head raw

// ---------------- GEMM: C[M,N] = act( [A0|A1][M,K] @ W[K,N] + bias ) -------
// A is split in two K-segments (handles concatenated inputs without copies).
// BM=BN=64, BK=16, 256 threads, 4x4 per-thread tile. M,N multiples of 64.
template <bool RELU>
__global__ __launch_bounds__(256) void gemm_bias(
    const float* __restrict__ A0, int lda0, int K0,
    const float* __restrict__ A1, int lda1, int K,
    const float* __restrict__ W, int ldw,
    const float* __restrict__ bias,
    float* __restrict__ C, int ldc)
{
    __shared__ float As[16][64];
    __shared__ float Ws[16][64];

    const int tid = threadIdx.x;
    const int tx = tid & 15;      // 0..15 -> cols
    const int ty = tid >> 4;      // 0..15 -> rows
    const int row0 = blockIdx.y * 64;
    const int col0 = blockIdx.x * 64;

    const int lm  = tid >> 2;          // A tile row 0..63
    const int lk4 = (tid & 3) * 4;     // A tile k base {0,4,8,12}
    const int wk  = tid >> 4;          // W tile k 0..15
    const int wn  = (tid & 15) * 4;    // W tile n base

    float acc[4][4] = {};

    for (int k0 = 0; k0 < K; k0 += 16) {
        // load A tile (scalar, segment-aware, K-guarded)
        const int arow = row0 + lm;
#pragma unroll
        for (int i = 0; i < 4; i++) {
            int kk = k0 + lk4 + i;
            float v = 0.f;
            if (kk < K0)       v = A0[(size_t)arow * lda0 + kk];
            else if (kk < K)   v = A1[(size_t)arow * lda1 + (kk - K0)];
            As[lk4 + i][lm] = v;
        }
        // load W tile (vectorized; N always multiple of 64)
        {
            int kk = k0 + wk;
            float4 wv = make_float4(0.f, 0.f, 0.f, 0.f);
            if (kk < K)
                wv = *reinterpret_cast<const float4*>(&W[(size_t)kk * ldw + col0 + wn]);
            *reinterpret_cast<float4*>(&Ws[wk][wn]) = wv;
        }
        __syncthreads();

#pragma unroll
        for (int k = 0; k < 16; k++) {
            float4 a4 = *reinterpret_cast<float4*>(&As[k][ty * 4]);
            float4 b4 = *reinterpret_cast<float4*>(&Ws[k][tx * 4]);
            float av[4] = {a4.x, a4.y, a4.z, a4.w};
            float bv[4] = {b4.x, b4.y, b4.z, b4.w};
#pragma unroll
            for (int i = 0; i < 4; i++)
#pragma unroll
                for (int j = 0; j < 4; j++)
                    acc[i][j] = fmaf(av[i], bv[j], acc[i][j]);
        }
        __syncthreads();
    }

    // epilogue
#pragma unroll
    for (int i = 0; i < 4; i++) {
        const int r = row0 + ty * 4 + i;
        const int cbase = col0 + tx * 4;
        float4 o;
        o.x = acc[i][0] + bias[cbase + 0];
        o.y = acc[i][1] + bias[cbase + 1];
        o.z = acc[i][2] + bias[cbase + 2];
        o.w = acc[i][3] + bias[cbase + 3];
        if (RELU) {
            o.x = fmaxf(o.x, 0.f); o.y = fmaxf(o.y, 0.f);
            o.z = fmaxf(o.z, 0.f); o.w = fmaxf(o.w, 0.f);
        }
        *reinterpret_cast<float4*>(&C[(size_t)r * ldc + cbase]) = o;
    }
}

// ---------------- GRU gate fusion -----------------------------------------
__device__ __forceinline__ float sigmoidf_(float x) { return 1.f / (1.f + expf(-x)); }

__global__ void gru_gate(const float* __restrict__ gi, const float* __restrict__ gh,
                         const float* __restrict__ hprev, float* __restrict__ belief_out)
{
    int idx = blockIdx.x * blockDim.x + threadIdx.x;   // 512*1024
    int b = idx >> 10;
    int j = idx & 1023;
    size_t base = (size_t)b * 3072;
    float ir = gi[base + j],        hr = gh[base + j];
    float iz = gi[base + 1024 + j], hz = gh[base + 1024 + j];
    float in_ = gi[base + 2048 + j], hn = gh[base + 2048 + j];
    float r = sigmoidf_(ir + hr);
    float z = sigmoidf_(iz + hz);
    float n = tanhf(in_ + r * hn);
    float h = hprev[(size_t)b * 1024 + j];
    belief_out[(size_t)b * 1024 + j] = (1.f - z) * n + z * h;
}

// ---------------- dist head: mean / softplus std / sampled state ----------
__global__ void dist_head(const float* __restrict__ y /* [512,512] */,
                          const float* __restrict__ noise /* [512,256] */,
                          float* __restrict__ mean_out,
                          float* __restrict__ sd_out,
                          float* __restrict__ state_out)
{
    int idx = blockIdx.x * blockDim.x + threadIdx.x;   // 512*256
    int b = idx >> 8;
    int c = idx & 255;
    float m = y[(size_t)b * 512 + c];
    float raw = y[(size_t)b * 512 + 256 + c];
    // softplus(x) = max(x,0) + log1p(exp(-|x|))
    float sd = fmaxf(raw, 0.f) + log1pf(expf(-fabsf(raw))) + 0.1f;
    float st = m + sd * noise[(size_t)b * 256 + c];
    mean_out[idx]  = m;
    sd_out[idx]    = sd;
    state_out[idx] = st;
}

// ---------------- launch ---------------------------------------------------
extern "C" void kernel_launch(void* const* d_in, const int* in_sizes, int n_in,
                              void* d_out, int out_size)
{
    const float* prev_state  = (const float*)d_in[0];
    const float* prev_belief = (const float*)d_in[1];
    const float* poses       = (const float*)d_in[2];   // [32,512,6]
    const float* observations= (const float*)d_in[3];   // [32,512,1024]
    const float* post_noise  = (const float*)d_in[4];   // [32,512,256]
    const float* prior_noise = (const float*)d_in[5];   // [32,512,256]
    const float* w_es  = (const float*)d_in[6];
    const float* b_es  = (const float*)d_in[7];
    const float* w_ih  = (const float*)d_in[8];
    const float* w_hh  = (const float*)d_in[9];
    const float* b_ih  = (const float*)d_in[10];
    const float* b_hh  = (const float*)d_in[11];
    const float* w_ebpo= (const float*)d_in[12];
    const float* b_ebpo= (const float*)d_in[13];
    const float* w_spo = (const float*)d_in[14];
    const float* b_spo = (const float*)d_in[15];
    const float* w_ebpr= (const float*)d_in[16];
    const float* b_ebpr= (const float*)d_in[17];
    const float* w_spr = (const float*)d_in[18];
    const float* b_spr = (const float*)d_in[19];

    float* out = (float*)d_out;

    // output layout: beliefs[32,512,1024], prior_states, prior_means,
    // prior_std_devs, posterior_states, posterior_means, posterior_std_devs
    const size_t SZB = (size_t)TSTEPS * BATCH * BELIEF;   // 16777216
    const size_t SZS = (size_t)TSTEPS * BATCH * STATE;    //  4194304
    float* out_belief = out;
    float* out_prs  = out + SZB;
    float* out_prm  = out + SZB + 1 * SZS;
    float* out_prsd = out + SZB + 2 * SZS;
    float* out_ps   = out + SZB + 3 * SZS;
    float* out_pm   = out + SZB + 4 * SZS;
    float* out_psd  = out + SZB + 5 * SZS;

    float *hidden, *gi, *gh, *hp, *hq, *ypo, *ypr;
    cudaGetSymbolAddress((void**)&hidden, g_hidden);
    cudaGetSymbolAddress((void**)&gi, g_gi);
    cudaGetSymbolAddress((void**)&gh, g_gh);
    cudaGetSymbolAddress((void**)&hp, g_hp);
    cudaGetSymbolAddress((void**)&hq, g_hq);
    cudaGetSymbolAddress((void**)&ypo, g_ypo);
    cudaGetSymbolAddress((void**)&ypr, g_ypr);

    const dim3 blk(256);
    const dim3 grid_es(BELIEF / 64, BATCH / 64);     // 16 x 8
    const dim3 grid_gru(3 * BELIEF / 64, BATCH / 64);// 48 x 8
    const dim3 grid_h(HIDDEN / 64, BATCH / 64);      // 16 x 8
    const dim3 grid_head(2 * STATE / 64, BATCH / 64);// 8 x 8

    for (int t = 0; t < TSTEPS; t++) {
        const float* post_s   = (t == 0) ? prev_state  : out_ps  + (size_t)(t - 1) * BATCH * STATE;
        const float* prior_s  = (t == 0) ? prev_state  : out_prs + (size_t)(t - 1) * BATCH * STATE;
        const float* belief_p = (t == 0) ? prev_belief : out_belief + (size_t)(t - 1) * BATCH * BELIEF;
        float* belief_t = out_belief + (size_t)t * BATCH * BELIEF;
        const float* obs_t  = observations + (size_t)t * BATCH * EMB;
        const float* pose_t = poses + (size_t)t * BATCH * 6;

        // hidden = relu([post_s, prior_s] @ w_es + b_es)
        gemm_bias<true><<<grid_es, blk>>>(post_s, STATE, STATE,
                                          prior_s, STATE, 2 * STATE,
                                          w_es, BELIEF, b_es, hidden, BELIEF);
        // gi = hidden @ w_ih + b_ih ; gh = belief_prev @ w_hh + b_hh
        gemm_bias<false><<<grid_gru, blk>>>(hidden, BELIEF, BELIEF,
                                            nullptr, 0, BELIEF,
                                            w_ih, 3 * BELIEF, b_ih, gi, 3 * BELIEF);
        gemm_bias<false><<<grid_gru, blk>>>(belief_p, BELIEF, BELIEF,
                                            nullptr, 0, BELIEF,
                                            w_hh, 3 * BELIEF, b_hh, gh, 3 * BELIEF);
        gru_gate<<<(BATCH * BELIEF) / 256, 256>>>(gi, gh, belief_p, belief_t);

        // posterior branch
        gemm_bias<true><<<grid_h, blk>>>(belief_t, BELIEF, BELIEF,
                                         obs_t, EMB, BELIEF + EMB,
                                         w_ebpo, HIDDEN, b_ebpo, hp, HIDDEN);
        gemm_bias<false><<<grid_head, blk>>>(hp, HIDDEN, HIDDEN,
                                             nullptr, 0, HIDDEN,
                                             w_spo, 2 * STATE, b_spo, ypo, 2 * STATE);
        dist_head<<<(BATCH * STATE) / 256, 256>>>(ypo,
                                                  post_noise + (size_t)t * BATCH * STATE,
                                                  out_pm  + (size_t)t * BATCH * STATE,
                                                  out_psd + (size_t)t * BATCH * STATE,
                                                  out_ps  + (size_t)t * BATCH * STATE);
        // prior branch (pose tiled x1)
        gemm_bias<true><<<grid_h, blk>>>(belief_t, BELIEF, BELIEF,
                                         pose_t, 6, BELIEF + 6,
                                         w_ebpr, HIDDEN, b_ebpr, hq, HIDDEN);
        gemm_bias<false><<<grid_head, blk>>>(hq, HIDDEN, HIDDEN,
                                             nullptr, 0, HIDDEN,
                                             w_spr, 2 * STATE, b_spr, ypr, 2 * STATE);
        dist_head<<<(BATCH * STATE) / 256, 256>>>(ypr,
                                                  prior_noise + (size_t)t * BATCH * STATE,
                                                  out_prm  + (size_t)t * BATCH * STATE,
                                                  out_prsd + (size_t)t * BATCH * STATE,
                                                  out_prs  + (size_t)t * BATCH * STATE);
    }
}

// round 3
// speedup vs baseline: 1.8535x; 1.8535x over previous
#include <cuda_runtime.h>
#include <cuda_bf16.h>
#include <stdint.h>
#include <math.h>

#define BATCH 512
#define TSTEPS 32
#define BELIEF 1024
#define STATE 256
#define HIDDEN 1024
#define EMB 1024

// GEMM tiling
#define BM 128
#define BN 128
#define BK 64
#define APAD 72                       // smem row stride (bf16 elems), pad avoids ldmatrix conflicts
#define ASZ (BM * APAD * 2)           // bytes per operand per stage = 18432
#define SMEM_TOTAL (4 * ASZ)          // A0,A1,B0,B1 = 73728

// ---------------- scratch (device globals; no allocations) ----------------
__device__ float g_gi[BATCH * 3 * BELIEF];
__device__ float g_gh[BATCH * 3 * BELIEF];
__device__ float g_ypo[BATCH * 2 * STATE];
__device__ float g_ypr[BATCH * 2 * STATE];

// split-bf16 activation buffers: [R, 3L], K-sections [hi | lo | hi]
__device__ __align__(256) __nv_bfloat16 g_sb_state[BATCH * 3 * 512];     // [ps|prs] per section
__device__ __align__(256) __nv_bfloat16 g_sb_hidden[BATCH * 3 * 1024];
__device__ __align__(256) __nv_bfloat16 g_sb_belief[BATCH * 3 * 1024];
__device__ __align__(256) __nv_bfloat16 g_sb_pose[BATCH * 3 * 64];       // 6 real cols, rest stays 0
__device__ __align__(256) __nv_bfloat16 g_sb_hp[BATCH * 3 * 1024];
__device__ __align__(256) __nv_bfloat16 g_sb_hq[BATCH * 3 * 1024];
__device__ __align__(256) __nv_bfloat16 g_sb_obs[(size_t)TSTEPS * BATCH * 3 * 1024];

// split-bf16 weights, transposed to [N, Kp] (n-major, k contiguous), sections [hi | hi | lo]
__device__ __align__(256) __nv_bfloat16 g_wb_es[1024 * 1536];
__device__ __align__(256) __nv_bfloat16 g_wb_ih[3072 * 3072];
__device__ __align__(256) __nv_bfloat16 g_wb_hh[3072 * 3072];
__device__ __align__(256) __nv_bfloat16 g_wb_ebpo[1024 * 6144];
__device__ __align__(256) __nv_bfloat16 g_wb_ebpr[1024 * 3264];
__device__ __align__(256) __nv_bfloat16 g_wb_spo[512 * 3072];
__device__ __align__(256) __nv_bfloat16 g_wb_spr[512 * 3072];

// ---------------- helpers ---------------------------------------------------
__device__ __forceinline__ uint32_t smem_u32(const void* p) {
    uint32_t a;
    asm("{ .reg .u64 t; cvta.to.shared.u64 t, %1; cvt.u32.u64 %0, t; }" : "=r"(a) : "l"(p));
    return a;
}

__device__ __forceinline__ void mma_bf16(float* c, const uint32_t* a, uint32_t b0, uint32_t b1) {
    asm volatile("mma.sync.aligned.m16n8k16.row.col.f32.bf16.bf16.f32 "
        "{%0,%1,%2,%3}, {%4,%5,%6,%7}, {%8,%9}, {%0,%1,%2,%3};"
        : "+f"(c[0]), "+f"(c[1]), "+f"(c[2]), "+f"(c[3])
        : "r"(a[0]), "r"(a[1]), "r"(a[2]), "r"(a[3]), "r"(b0), "r"(b1));
}

struct GemmP {
    const __nv_bfloat16* A0;
    const __nv_bfloat16* A1;
    const __nv_bfloat16* Wb;
    const float* bias;
    float* C;
    __nv_bfloat16* Csp;
    int K1, K2, L, Kp, ldc, N;
};

// ---------------- tensor-core GEMM (mma.sync bf16, split-K' scheme) --------
// C[M=512, N] = act( A @ W + bias ). A pre-split bf16: A0 [M, 3*K1], optional
// A1 [M, 3*K2]; k' col mapping: sec = k'/L, rb = k' - sec*L;
//   rb <  K1 -> A0[:, sec*K1 + rb]
//   rb >= K1 -> A1[:, sec*K2 + rb-K1]
// Wb [N, Kp=3L] n-major. blockIdx.z selects p0/p1 (merged sibling GEMMs).
template <bool RELU, bool F32OUT, bool SPOUT>
__global__ __launch_bounds__(256, 2) void gemm_mma(GemmP p0, GemmP p1)
{
    extern __shared__ char smem[];
    const GemmP p = (blockIdx.z == 0) ? p0 : p1;
    const int tid = threadIdx.x;
    const int wid = tid >> 5, lane = tid & 31;
    const int row0 = blockIdx.y * BM, col0 = blockIdx.x * BN;
    const uint32_t sbase = smem_u32(smem);

    // ---- loader config: thread -> (row, k-half) ----
    const int lrow = tid >> 1;
    const int lhalf = (tid & 1) * 32;
    const __nv_bfloat16* a0r = p.A0 + (size_t)(row0 + lrow) * (3 * p.K1);
    const __nv_bfloat16* a1r = (p.A1 != nullptr)
        ? (p.A1 + (size_t)(row0 + lrow) * (3 * p.K2)) : (const __nv_bfloat16*)0;
    const __nv_bfloat16* wr = p.Wb + (size_t)(col0 + lrow) * p.Kp;
    const uint32_t dA = sbase + lrow * (APAD * 2) + lhalf * 2;
    const uint32_t dB = sbase + 2 * ASZ + lrow * (APAD * 2) + lhalf * 2;

    const int nkt = p.Kp / BK;

    auto issue = [&](int i) {
        const int st = i & 1;
        const int kp = i * BK + lhalf;
        const int sec = (kp >= p.L) + (kp >= 2 * p.L);
        const int rb = kp - sec * p.L;
        const __nv_bfloat16* as = (rb < p.K1) ? (a0r + sec * p.K1 + rb)
                                              : (a1r + sec * p.K2 + (rb - p.K1));
        const __nv_bfloat16* bs = wr + i * BK + lhalf;
        const uint32_t da = dA + st * ASZ;
        const uint32_t db = dB + st * ASZ;
        #pragma unroll
        for (int j = 0; j < 4; j++) {
            asm volatile("cp.async.cg.shared.global [%0], [%1], 16;" :: "r"(da + j * 16), "l"(as + j * 8));
            asm volatile("cp.async.cg.shared.global [%0], [%1], 16;" :: "r"(db + j * 16), "l"(bs + j * 8));
        }
        asm volatile("cp.async.commit_group;" ::: "memory");
    };

    // ---- compute config: warp grid 4(M) x 2(N); warp tile 32x64 ----
    const int wm = wid & 3, wn = wid >> 2;
    const uint32_t lmrow = (lane & 15);
    const uint32_t lkoff = (lane >> 4) * 16;  // bytes (8 bf16)
    const uint32_t aBase = sbase + (wm * 32 + lmrow) * (APAD * 2) + lkoff;
    const uint32_t bBase = sbase + 2 * ASZ + (wn * 64 + lmrow) * (APAD * 2) + lkoff;

    float acc[2][8][4];
    #pragma unroll
    for (int i = 0; i < 2; i++)
        #pragma unroll
        for (int j = 0; j < 8; j++)
            #pragma unroll
            for (int q = 0; q < 4; q++) acc[i][j][q] = 0.f;

    issue(0);
    for (int i = 0; i < nkt; i++) {
        if (i + 1 < nkt) {
            issue(i + 1);
            asm volatile("cp.async.wait_group 1;" ::: "memory");
        } else {
            asm volatile("cp.async.wait_group 0;" ::: "memory");
        }
        __syncthreads();
        const int st = i & 1;
        const uint32_t aS = aBase + st * ASZ;
        const uint32_t bS = bBase + st * ASZ;
        #pragma unroll
        for (int ks = 0; ks < 4; ks++) {
            uint32_t a[2][4];
            #pragma unroll
            for (int mf = 0; mf < 2; mf++) {
                asm volatile("ldmatrix.sync.aligned.m8n8.x4.shared.b16 {%0,%1,%2,%3}, [%4];"
                    : "=r"(a[mf][0]), "=r"(a[mf][1]), "=r"(a[mf][2]), "=r"(a[mf][3])
                    : "r"(aS + mf * 16 * (APAD * 2) + ks * 32));
            }
            #pragma unroll
            for (int nb = 0; nb < 4; nb++) {
                uint32_t b[4];
                asm volatile("ldmatrix.sync.aligned.m8n8.x4.shared.b16 {%0,%1,%2,%3}, [%4];"
                    : "=r"(b[0]), "=r"(b[1]), "=r"(b[2]), "=r"(b[3])
                    : "r"(bS + nb * 16 * (APAD * 2) + ks * 32));
                #pragma unroll
                for (int mf = 0; mf < 2; mf++) {
                    mma_bf16(acc[mf][2 * nb + 0], a[mf], b[0], b[2]);
                    mma_bf16(acc[mf][2 * nb + 1], a[mf], b[1], b[3]);
                }
            }
        }
        __syncthreads();
    }

    // ---- epilogue ----
    #pragma unroll
    for (int mf = 0; mf < 2; mf++) {
        #pragma unroll
        for (int nf = 0; nf < 8; nf++) {
            const int row_ = row0 + wm * 32 + mf * 16 + (lane >> 2);
            const int col_ = col0 + wn * 64 + nf * 8 + (lane & 3) * 2;
            const float b0 = p.bias[col_], b1 = p.bias[col_ + 1];
            #pragma unroll
            for (int rh = 0; rh < 2; rh++) {
                float v0 = acc[mf][nf][rh * 2 + 0] + b0;
                float v1 = acc[mf][nf][rh * 2 + 1] + b1;
                if (RELU) { v0 = fmaxf(v0, 0.f); v1 = fmaxf(v1, 0.f); }
                const int rr = row_ + rh * 8;
                if (F32OUT) {
                    *reinterpret_cast<float2*>(&p.C[(size_t)rr * p.ldc + col_]) = make_float2(v0, v1);
                }
                if (SPOUT) {
                    __nv_bfloat16 h0 = __float2bfloat16(v0), h1 = __float2bfloat16(v1);
                    __nv_bfloat16 l0 = __float2bfloat16(v0 - __bfloat162float(h0));
                    __nv_bfloat16 l1 = __float2bfloat16(v1 - __bfloat162float(h1));
                    ushort2 hu; hu.x = __bfloat16_as_ushort(h0); hu.y = __bfloat16_as_ushort(h1);
                    ushort2 lu; lu.x = __bfloat16_as_ushort(l0); lu.y = __bfloat16_as_ushort(l1);
                    ushort* cs = reinterpret_cast<ushort*>(p.Csp);
                    const size_t base = (size_t)rr * 3 * p.N + col_;
                    *reinterpret_cast<ushort2*>(&cs[base]) = hu;
                    *reinterpret_cast<ushort2*>(&cs[base + p.N]) = lu;
                    *reinterpret_cast<ushort2*>(&cs[base + 2 * p.N]) = hu;
                }
            }
        }
    }
}

// ---------------- weight conversion: W[K,N] f32 -> Wb[N, Kp=3L] bf16 -------
// k' sections [hi, hi, lo]; rows >= Keff zero.
__global__ void convert_w(const float* __restrict__ W, int N, int Keff, int L,
                          int Kp, __nv_bfloat16* __restrict__ out)
{
    __shared__ unsigned short tile[32][33];
    int k0 = blockIdx.x * 32, n0 = blockIdx.y * 32;
    int tx = threadIdx.x, ty = threadIdx.y;  // 32 x 8
    #pragma unroll
    for (int q = 0; q < 4; q++) {
        int kl = ty + q * 8;
        int kp = k0 + kl;
        int s = kp / L;
        int rr = kp - s * L;
        float v = (rr < Keff) ? W[(size_t)rr * N + n0 + tx] : 0.f;
        __nv_bfloat16 b;
        if (s == 2) {
            __nv_bfloat16 h = __float2bfloat16(v);
            b = __float2bfloat16(v - __bfloat162float(h));
        } else {
            b = __float2bfloat16(v);
        }
        tile[kl][tx] = __bfloat16_as_ushort(b);
    }
    __syncthreads();
    #pragma unroll
    for (int q = 0; q < 4; q++) {
        int nl = ty + q * 8;
        reinterpret_cast<unsigned short*>(out)[(size_t)(n0 + nl) * Kp + k0 + tx] = tile[tx][nl];
    }
}

// ---------------- activation split helpers ----------------------------------
// src [R, L] f32 -> dst [R, 3L] bf16 sections [hi|lo|hi]
__global__ void split_rows(const float* __restrict__ src, __nv_bfloat16* __restrict__ dst, int L)
{
    int r = blockIdx.y;
    int c = blockIdx.x * 256 + threadIdx.x;
    float v = src[(size_t)r * L + c];
    __nv_bfloat16 h = __float2bfloat16(v);
    __nv_bfloat16 l = __float2bfloat16(v - __bfloat162float(h));
    size_t o = (size_t)r * 3 * L + c;
    dst[o] = h; dst[o + L] = l; dst[o + 2 * L] = h;
}

// prev_state -> sb_state (both ps and prs halves = prev_state)
__global__ void split_state0(const float* __restrict__ ps, __nv_bfloat16* __restrict__ dst)
{
    int idx = blockIdx.x * 256 + threadIdx.x;  // 512*256
    int b = idx >> 8, c = idx & 255;
    float v = ps[idx];
    __nv_bfloat16 h = __float2bfloat16(v);
    __nv_bfloat16 l = __float2bfloat16(v - __bfloat162float(h));
    size_t base = (size_t)b * 1536;
    dst[base + c] = h;        dst[base + 256 + c] = h;
    dst[base + 512 + c] = l;  dst[base + 768 + c] = l;
    dst[base + 1024 + c] = h; dst[base + 1280 + c] = h;
}

// ---------------- GRU gate (+ belief/pose split) ----------------------------
__device__ __forceinline__ float sigmoidf_(float x) { return 1.f / (1.f + expf(-x)); }

__global__ void gru_gate(const float* __restrict__ gi, const float* __restrict__ gh,
                         const float* __restrict__ hprev, const float* __restrict__ pose_t,
                         float* __restrict__ belief_out,
                         __nv_bfloat16* __restrict__ sb_belief,
                         __nv_bfloat16* __restrict__ sb_pose)
{
    int idx = blockIdx.x * blockDim.x + threadIdx.x;
    int b = idx >> 10;
    int j = idx & 1023;
    size_t base = (size_t)b * 3072;
    float ir = gi[base + j],         hr = gh[base + j];
    float iz = gi[base + 1024 + j],  hz = gh[base + 1024 + j];
    float in_ = gi[base + 2048 + j], hn = gh[base + 2048 + j];
    float rg = sigmoidf_(ir + hr);
    float z = sigmoidf_(iz + hz);
    float n = tanhf(in_ + rg * hn);
    float h = hprev[(size_t)b * 1024 + j];
    float hv = (1.f - z) * n + z * h;
    belief_out[(size_t)b * 1024 + j] = hv;
    __nv_bfloat16 bh = __float2bfloat16(hv);
    __nv_bfloat16 bl = __float2bfloat16(hv - __bfloat162float(bh));
    sb_belief[base + j] = bh;
    sb_belief[base + 1024 + j] = bl;
    sb_belief[base + 2048 + j] = bh;
    if (j < 6) {
        float pv = pose_t[b * 6 + j];
        __nv_bfloat16 ph = __float2bfloat16(pv);
        __nv_bfloat16 pl = __float2bfloat16(pv - __bfloat162float(ph));
        size_t pb = (size_t)b * 192;
        sb_pose[pb + j] = ph;
        sb_pose[pb + 64 + j] = pl;
        sb_pose[pb + 128 + j] = ph;
    }
}

// ---------------- merged dist heads (+ state split) -------------------------
__global__ void dist_head2(const float* __restrict__ ypo, const float* __restrict__ ypr,
                           const float* __restrict__ pn, const float* __restrict__ rn,
                           float* __restrict__ pm, float* __restrict__ psd, float* __restrict__ ps,
                           float* __restrict__ prm, float* __restrict__ prsd, float* __restrict__ prs,
                           __nv_bfloat16* __restrict__ sb_state)
{
    int i2 = blockIdx.x * 256 + threadIdx.x;  // 2*512*256
    int half = i2 >> 17;
    int idx = i2 & 131071;
    int b = idx >> 8, c = idx & 255;
    const float* y = half ? ypr : ypo;
    const float* nz = half ? rn : pn;
    float m = y[(size_t)b * 512 + c];
    float raw = y[(size_t)b * 512 + 256 + c];
    float sd = fmaxf(raw, 0.f) + log1pf(expf(-fabsf(raw))) + 0.1f;
    float st = m + sd * nz[idx];
    if (half) { prm[idx] = m; prsd[idx] = sd; prs[idx] = st; }
    else      { pm[idx] = m;  psd[idx] = sd;  ps[idx] = st; }
    __nv_bfloat16 h = __float2bfloat16(st);
    __nv_bfloat16 l = __float2bfloat16(st - __bfloat162float(h));
    int off = half ? 256 : 0;
    size_t base = (size_t)b * 1536 + off + c;
    sb_state[base] = h;
    sb_state[base + 512] = l;
    sb_state[base + 1024] = h;
}

// ---------------- launch -----------------------------------------------------
extern "C" void kernel_launch(void* const* d_in, const int* in_sizes, int n_in,
                              void* d_out, int out_size)
{
    const float* prev_state   = (const float*)d_in[0];
    const float* prev_belief  = (const float*)d_in[1];
    const float* poses        = (const float*)d_in[2];
    const float* observations = (const float*)d_in[3];
    const float* post_noise   = (const float*)d_in[4];
    const float* prior_noise  = (const float*)d_in[5];
    const float* w_es   = (const float*)d_in[6];
    const float* b_es   = (const float*)d_in[7];
    const float* w_ih   = (const float*)d_in[8];
    const float* w_hh   = (const float*)d_in[9];
    const float* b_ih   = (const float*)d_in[10];
    const float* b_hh   = (const float*)d_in[11];
    const float* w_ebpo = (const float*)d_in[12];
    const float* b_ebpo = (const float*)d_in[13];
    const float* w_spo  = (const float*)d_in[14];
    const float* b_spo  = (const float*)d_in[15];
    const float* w_ebpr = (const float*)d_in[16];
    const float* b_ebpr = (const float*)d_in[17];
    const float* w_spr  = (const float*)d_in[18];
    const float* b_spr  = (const float*)d_in[19];

    float* out = (float*)d_out;
    const size_t SZB = (size_t)TSTEPS * BATCH * BELIEF;
    const size_t SZS = (size_t)TSTEPS * BATCH * STATE;
    float* out_belief = out;
    float* out_prs  = out + SZB;
    float* out_prm  = out + SZB + 1 * SZS;
    float* out_prsd = out + SZB + 2 * SZS;
    float* out_ps   = out + SZB + 3 * SZS;
    float* out_pm   = out + SZB + 4 * SZS;
    float* out_psd  = out + SZB + 5 * SZS;

    float *gi, *gh, *ypo, *ypr;
    cudaGetSymbolAddress((void**)&gi, g_gi);
    cudaGetSymbolAddress((void**)&gh, g_gh);
    cudaGetSymbolAddress((void**)&ypo, g_ypo);
    cudaGetSymbolAddress((void**)&ypr, g_ypr);

    __nv_bfloat16 *sb_state, *sb_hidden, *sb_belief, *sb_pose, *sb_hp, *sb_hq, *sb_obs;
    cudaGetSymbolAddress((void**)&sb_state, g_sb_state);
    cudaGetSymbolAddress((void**)&sb_hidden, g_sb_hidden);
    cudaGetSymbolAddress((void**)&sb_belief, g_sb_belief);
    cudaGetSymbolAddress((void**)&sb_pose, g_sb_pose);
    cudaGetSymbolAddress((void**)&sb_hp, g_sb_hp);
    cudaGetSymbolAddress((void**)&sb_hq, g_sb_hq);
    cudaGetSymbolAddress((void**)&sb_obs, g_sb_obs);

    __nv_bfloat16 *wb_es, *wb_ih, *wb_hh, *wb_ebpo, *wb_ebpr, *wb_spo, *wb_spr;
    cudaGetSymbolAddress((void**)&wb_es, g_wb_es);
    cudaGetSymbolAddress((void**)&wb_ih, g_wb_ih);
    cudaGetSymbolAddress((void**)&wb_hh, g_wb_hh);
    cudaGetSymbolAddress((void**)&wb_ebpo, g_wb_ebpo);
    cudaGetSymbolAddress((void**)&wb_ebpr, g_wb_ebpr);
    cudaGetSymbolAddress((void**)&wb_spo, g_wb_spo);
    cudaGetSymbolAddress((void**)&wb_spr, g_wb_spr);

    cudaFuncSetAttribute(gemm_mma<true, false, true>,
                         cudaFuncAttributeMaxDynamicSharedMemorySize, SMEM_TOTAL);
    cudaFuncSetAttribute(gemm_mma<false, true, false>,
                         cudaFuncAttributeMaxDynamicSharedMemorySize, SMEM_TOTAL);

    // ---- upfront conversions ----
    dim3 cblk(32, 8);
    convert_w<<<dim3(48, 32), cblk>>>(w_es,   1024, 512,  512,  1536, wb_es);
    convert_w<<<dim3(96, 96), cblk>>>(w_ih,   3072, 1024, 1024, 3072, wb_ih);
    convert_w<<<dim3(96, 96), cblk>>>(w_hh,   3072, 1024, 1024, 3072, wb_hh);
    convert_w<<<dim3(192, 32), cblk>>>(w_ebpo, 1024, 2048, 2048, 6144, wb_ebpo);
    convert_w<<<dim3(102, 32), cblk>>>(w_ebpr, 1024, 1030, 1088, 3264, wb_ebpr);
    convert_w<<<dim3(96, 16), cblk>>>(w_spo,  512,  1024, 1024, 3072, wb_spo);
    convert_w<<<dim3(96, 16), cblk>>>(w_spr,  512,  1024, 1024, 3072, wb_spr);
    split_rows<<<dim3(4, TSTEPS * BATCH), 256>>>(observations, sb_obs, 1024);
    split_rows<<<dim3(4, BATCH), 256>>>(prev_belief, sb_belief, 1024);
    split_state0<<<512, 256>>>(prev_state, sb_state);

    // ---- GEMM param sets ----
    GemmP pes  = { sb_state,  nullptr, wb_es,   b_es,   nullptr, sb_hidden, 512,  0,    512,  1536, 0,    1024 };
    GemmP pgi  = { sb_hidden, nullptr, wb_ih,   b_ih,   gi,      nullptr,   1024, 0,    1024, 3072, 3072, 3072 };
    GemmP pgh  = { sb_belief, nullptr, wb_hh,   b_hh,   gh,      nullptr,   1024, 0,    1024, 3072, 3072, 3072 };
    GemmP pep  = { sb_belief, nullptr, wb_ebpo, b_ebpo, nullptr, sb_hp,     1024, 1024, 2048, 6144, 0,    1024 };
    GemmP peq  = { sb_belief, sb_pose, wb_ebpr, b_ebpr, nullptr, sb_hq,     1024, 64,   1088, 3264, 0,    1024 };
    GemmP pso  = { sb_hp,     nullptr, wb_spo,  b_spo,  ypo,     nullptr,   1024, 0,    1024, 3072, 512,  512 };
    GemmP psr  = { sb_hq,     nullptr, wb_spr,  b_spr,  ypr,     nullptr,   1024, 0,    1024, 3072, 512,  512 };

    for (int t = 0; t < TSTEPS; t++) {
        const float* belief_p = (t == 0) ? prev_belief : out_belief + (size_t)(t - 1) * BATCH * BELIEF;
        float* belief_t = out_belief + (size_t)t * BATCH * BELIEF;
        const float* pose_t = poses + (size_t)t * BATCH * 6;
        pep.A1 = sb_obs + (size_t)t * BATCH * 3072;

        gemm_mma<true, false, true><<<dim3(8, 4, 1), 256, SMEM_TOTAL>>>(pes, pes);
        gemm_mma<false, true, false><<<dim3(24, 4, 2), 256, SMEM_TOTAL>>>(pgi, pgh);
        gru_gate<<<2048, 256>>>(gi, gh, belief_p, pose_t, belief_t, sb_belief, sb_pose);
        gemm_mma<true, false, true><<<dim3(8, 4, 2), 256, SMEM_TOTAL>>>(pep, peq);
        gemm_mma<false, true, false><<<dim3(4, 4, 2), 256, SMEM_TOTAL>>>(pso, psr);
        dist_head2<<<1024, 256>>>(ypo, ypr,
                                  post_noise + (size_t)t * BATCH * STATE,
                                  prior_noise + (size_t)t * BATCH * STATE,
                                  out_pm  + (size_t)t * BATCH * STATE,
                                  out_psd + (size_t)t * BATCH * STATE,
                                  out_ps  + (size_t)t * BATCH * STATE,
                                  out_prm  + (size_t)t * BATCH * STATE,
                                  out_prsd + (size_t)t * BATCH * STATE,
                                  out_prs  + (size_t)t * BATCH * STATE,
                                  sb_state);
    }
}

// round 5
// speedup vs baseline: 3.6275x; 1.9571x over previous
#include <cuda_runtime.h>
#include <cuda_bf16.h>
#include <stdint.h>
#include <math.h>

#define BATCH 512
#define TSTEPS 32
#define BELIEF 1024
#define STATE 256
#define HIDDEN 1024
#define EMB 1024

#define BK 64
#define BN 128
#define APAD 72                         // bf16 elems per smem row (144B)
#define ROWB (APAD * 2)                 // 144 bytes
#define NSTAGE 3

// ---------------- scratch ----------------------------------------------------
__device__ float g_gi[BATCH * 3 * BELIEF];
__device__ float g_gh[BATCH * 3 * BELIEF];
__device__ float g_ypo[BATCH * 2 * STATE];
__device__ float g_ypo2[BATCH * 2 * STATE];
__device__ float g_ypr[BATCH * 2 * STATE];
__device__ float g_ypr2[BATCH * 2 * STATE];

// split-bf16 activations: [R, 3L], sections [hi | lo | hi]
__device__ __align__(256) __nv_bfloat16 g_sb_state[BATCH * 3 * 512];
__device__ __align__(256) __nv_bfloat16 g_sb_hidden[BATCH * 3 * 1024];
__device__ __align__(256) __nv_bfloat16 g_sb_belief[BATCH * 3 * 1024];
__device__ __align__(256) __nv_bfloat16 g_sb_pose[BATCH * 3 * 64];
__device__ __align__(256) __nv_bfloat16 g_sb_hp[BATCH * 3 * 1024];
__device__ __align__(256) __nv_bfloat16 g_sb_hq[BATCH * 3 * 1024];
__device__ __align__(256) __nv_bfloat16 g_sb_obs[(size_t)TSTEPS * BATCH * 3 * 1024];

// split-bf16 weights [N, Kp=3L], sections [hi | hi | lo]
__device__ __align__(256) __nv_bfloat16 g_wb_es[1024 * 1536];
__device__ __align__(256) __nv_bfloat16 g_wb_ih[3072 * 3072];
__device__ __align__(256) __nv_bfloat16 g_wb_hh[3072 * 3072];
__device__ __align__(256) __nv_bfloat16 g_wb_ebpo[1024 * 6144];
__device__ __align__(256) __nv_bfloat16 g_wb_ebpr[1024 * 3264];
__device__ __align__(256) __nv_bfloat16 g_wb_spo[512 * 3072];
__device__ __align__(256) __nv_bfloat16 g_wb_spr[512 * 3072];

// ---------------- helpers ----------------------------------------------------
__device__ __forceinline__ uint32_t smem_u32(const void* p) {
    uint32_t a;
    asm("{ .reg .u64 t; cvta.to.shared.u64 t, %1; cvt.u32.u64 %0, t; }" : "=r"(a) : "l"(p));
    return a;
}
__device__ __forceinline__ void mma_bf16(float* c, const uint32_t* a, uint32_t b0, uint32_t b1) {
    asm volatile("mma.sync.aligned.m16n8k16.row.col.f32.bf16.bf16.f32 "
        "{%0,%1,%2,%3}, {%4,%5,%6,%7}, {%8,%9}, {%0,%1,%2,%3};"
        : "+f"(c[0]), "+f"(c[1]), "+f"(c[2]), "+f"(c[3])
        : "r"(a[0]), "r"(a[1]), "r"(a[2]), "r"(a[3]), "r"(b0), "r"(b1));
}

struct GemmP {
    const __nv_bfloat16* A0;
    const __nv_bfloat16* A1;
    const __nv_bfloat16* Wb;
    const float* bias;
    float* C;
    float* C2;                     // split-K partial (no bias)
    __nv_bfloat16* Csp;
    int K1, K2, L, Kp, ldc, N;
};

// ---------------- tensor-core GEMM -------------------------------------------
// C[512, N] = act( A @ W + bias ), split-K' scheme (Kp = 3L).
// BMt in {64,128}; 256 threads, warp grid 4(M) x 2(N), warp tile (BMt/4) x 64.
template <int BMT, bool RELU, bool F32OUT, bool SPOUT, bool SPLITK>
__global__ __launch_bounds__(256, 2) void gemm_mma(GemmP p0, GemmP p1)
{
    constexpr int MF = BMT / 64;              // 16-row m-fragments per warp
    constexpr int ASZ = BMT * ROWB;
    constexpr int BSZ = BN * ROWB;
    extern __shared__ char smem[];
    const int z = blockIdx.z;
    const GemmP p = ((SPLITK ? (z >> 1) : z) != 0) ? p1 : p0;
    const int nkt_all = p.Kp / BK;
    const int nkt = SPLITK ? (nkt_all >> 1) : nkt_all;
    const int kb = SPLITK ? (z & 1) * nkt : 0;
    float* Cout = (SPLITK && (z & 1)) ? p.C2 : p.C;
    const bool addBias = !(SPLITK && (z & 1));

    const int tid = threadIdx.x;
    const int wid = tid >> 5, lane = tid & 31;
    const int row0 = blockIdx.y * BMT, col0 = blockIdx.x * BN;
    const uint32_t sbase = smem_u32(smem);

    // ---- loader ----
    auto issue = [&](int i, int slot) {
        const int kp = i * BK;
        const int sec = (kp >= p.L) + (kp >= 2 * p.L);
        const int rb = kp - sec * p.L;
        const bool useA0 = (rb < p.K1);
        const __nv_bfloat16* abase = useA0
            ? (p.A0 + (size_t)row0 * (3 * p.K1) + sec * p.K1 + rb)
            : (p.A1 + (size_t)row0 * (3 * p.K2) + sec * p.K2 + (rb - p.K1));
        const int astr = useA0 ? 3 * p.K1 : 3 * p.K2;
        const uint32_t da = sbase + slot * ASZ;
        #pragma unroll
        for (int q = 0; q < BMT * 8 / 256; q++) {
            int idx = tid + q * 256;
            int r = idx >> 3, c = idx & 7;
            asm volatile("cp.async.cg.shared.global [%0], [%1], 16;"
                :: "r"(da + r * ROWB + c * 16), "l"(abase + (size_t)r * astr + c * 8));
        }
        const __nv_bfloat16* bbase = p.Wb + (size_t)col0 * p.Kp + i * BK;
        const uint32_t db = sbase + NSTAGE * ASZ + slot * BSZ;
        #pragma unroll
        for (int q = 0; q < BN * 8 / 256; q++) {
            int idx = tid + q * 256;
            int r = idx >> 3, c = idx & 7;
            asm volatile("cp.async.cg.shared.global [%0], [%1], 16;"
                :: "r"(db + r * ROWB + c * 16), "l"(bbase + (size_t)r * p.Kp + c * 8));
        }
        asm volatile("cp.async.commit_group;" ::: "memory");
    };

    const int wm = wid & 3, wn = wid >> 2;
    const uint32_t lrow = lane & 15;
    const uint32_t lk16 = (lane >> 4) * 16;

    float acc[MF][8][4];
    #pragma unroll
    for (int mf = 0; mf < MF; mf++)
        #pragma unroll
        for (int j = 0; j < 8; j++)
            #pragma unroll
            for (int q = 0; q < 4; q++) acc[mf][j][q] = 0.f;

    issue(kb + 0, 0);
    issue(kb + 1, 1);

    for (int it = 0; it < nkt; it++) {
        asm volatile("cp.async.wait_group 1;" ::: "memory");
        __syncthreads();
        const int slot = it % NSTAGE;
        const uint32_t aS = sbase + slot * ASZ + (wm * 16 * MF + lrow) * ROWB + lk16;
        const uint32_t bS = sbase + NSTAGE * ASZ + slot * BSZ + (wn * 64 + lrow) * ROWB + lk16;
        #pragma unroll
        for (int ks = 0; ks < 4; ks++) {
            uint32_t a[MF][4];
            #pragma unroll
            for (int mf = 0; mf < MF; mf++)
                asm volatile("ldmatrix.sync.aligned.m8n8.x4.shared.b16 {%0,%1,%2,%3}, [%4];"
                    : "=r"(a[mf][0]), "=r"(a[mf][1]), "=r"(a[mf][2]), "=r"(a[mf][3])
                    : "r"(aS + mf * 16 * ROWB + ks * 32));
            #pragma unroll
            for (int nb = 0; nb < 4; nb++) {
                uint32_t b[4];
                asm volatile("ldmatrix.sync.aligned.m8n8.x4.shared.b16 {%0,%1,%2,%3}, [%4];"
                    : "=r"(b[0]), "=r"(b[1]), "=r"(b[2]), "=r"(b[3])
                    : "r"(bS + nb * 16 * ROWB + ks * 32));
                #pragma unroll
                for (int mf = 0; mf < MF; mf++) {
                    mma_bf16(acc[mf][2 * nb + 0], a[mf], b[0], b[2]);
                    mma_bf16(acc[mf][2 * nb + 1], a[mf], b[1], b[3]);
                }
            }
        }
        if (it + 2 < nkt) issue(kb + it + 2, (it + 2) % NSTAGE);
        else asm volatile("cp.async.commit_group;" ::: "memory");
    }

    // ---- epilogue ----
    #pragma unroll
    for (int mf = 0; mf < MF; mf++) {
        #pragma unroll
        for (int nf = 0; nf < 8; nf++) {
            const int row_ = row0 + wm * 16 * MF + mf * 16 + (lane >> 2);
            const int col_ = col0 + wn * 64 + nf * 8 + (lane & 3) * 2;
            const float b0 = addBias ? p.bias[col_] : 0.f;
            const float b1 = addBias ? p.bias[col_ + 1] : 0.f;
            #pragma unroll
            for (int rh = 0; rh < 2; rh++) {
                float v0 = acc[mf][nf][rh * 2 + 0] + b0;
                float v1 = acc[mf][nf][rh * 2 + 1] + b1;
                if (RELU) { v0 = fmaxf(v0, 0.f); v1 = fmaxf(v1, 0.f); }
                const int rr = row_ + rh * 8;
                if (F32OUT)
                    *reinterpret_cast<float2*>(&Cout[(size_t)rr * p.ldc + col_]) = make_float2(v0, v1);
                if (SPOUT) {
                    __nv_bfloat16 h0 = __float2bfloat16(v0), h1 = __float2bfloat16(v1);
                    __nv_bfloat16 l0 = __float2bfloat16(v0 - __bfloat162float(h0));
                    __nv_bfloat16 l1 = __float2bfloat16(v1 - __bfloat162float(h1));
                    ushort2 hu; hu.x = __bfloat16_as_ushort(h0); hu.y = __bfloat16_as_ushort(h1);
                    ushort2 lu; lu.x = __bfloat16_as_ushort(l0); lu.y = __bfloat16_as_ushort(l1);
                    ushort* cs = reinterpret_cast<ushort*>(p.Csp);
                    const size_t base = (size_t)rr * 3 * p.N + col_;
                    *reinterpret_cast<ushort2*>(&cs[base]) = hu;
                    *reinterpret_cast<ushort2*>(&cs[base + p.N]) = lu;
                    *reinterpret_cast<ushort2*>(&cs[base + 2 * p.N]) = hu;
                }
            }
        }
    }
}

// ---------------- weight conversion -----------------------------------------
__global__ void convert_w(const float* __restrict__ W, int N, int Keff, int L,
                          int Kp, __nv_bfloat16* __restrict__ out)
{
    __shared__ unsigned short tile[32][33];
    int k0 = blockIdx.x * 32, n0 = blockIdx.y * 32;
    int tx = threadIdx.x, ty = threadIdx.y;
    #pragma unroll
    for (int q = 0; q < 4; q++) {
        int kl = ty + q * 8;
        int kp = k0 + kl;
        int s = kp / L;
        int rr = kp - s * L;
        float v = (rr < Keff) ? W[(size_t)rr * N + n0 + tx] : 0.f;
        __nv_bfloat16 b;
        if (s == 2) {
            __nv_bfloat16 h = __float2bfloat16(v);
            b = __float2bfloat16(v - __bfloat162float(h));
        } else b = __float2bfloat16(v);
        tile[kl][tx] = __bfloat16_as_ushort(b);
    }
    __syncthreads();
    #pragma unroll
    for (int q = 0; q < 4; q++) {
        int nl = ty + q * 8;
        reinterpret_cast<unsigned short*>(out)[(size_t)(n0 + nl) * Kp + k0 + tx] = tile[tx][nl];
    }
}

// ---------------- activation splits ------------------------------------------
__global__ void split_rows(const float* __restrict__ src, __nv_bfloat16* __restrict__ dst, int L)
{
    int r = blockIdx.y;
    int c = blockIdx.x * 256 + threadIdx.x;
    float v = src[(size_t)r * L + c];
    __nv_bfloat16 h = __float2bfloat16(v);
    __nv_bfloat16 l = __float2bfloat16(v - __bfloat162float(h));
    size_t o = (size_t)r * 3 * L + c;
    dst[o] = h; dst[o + L] = l; dst[o + 2 * L] = h;
}
__global__ void split_state0(const float* __restrict__ ps, __nv_bfloat16* __restrict__ dst)
{
    int idx = blockIdx.x * 256 + threadIdx.x;
    int b = idx >> 8, c = idx & 255;
    float v = ps[idx];
    __nv_bfloat16 h = __float2bfloat16(v);
    __nv_bfloat16 l = __float2bfloat16(v - __bfloat162float(h));
    size_t base = (size_t)b * 1536;
    dst[base + c] = h;        dst[base + 256 + c] = h;
    dst[base + 512 + c] = l;  dst[base + 768 + c] = l;
    dst[base + 1024 + c] = h; dst[base + 1280 + c] = h;
}

// ---------------- GRU gate ---------------------------------------------------
__device__ __forceinline__ float sigmoidf_(float x) { return 1.f / (1.f + expf(-x)); }

__global__ void gru_gate(const float* __restrict__ gi, const float* __restrict__ gh,
                         const float* __restrict__ hprev, const float* __restrict__ pose_t,
                         float* __restrict__ belief_out,
                         __nv_bfloat16* __restrict__ sb_belief,
                         __nv_bfloat16* __restrict__ sb_pose)
{
    int idx = blockIdx.x * blockDim.x + threadIdx.x;
    int b = idx >> 10;
    int j = idx & 1023;
    size_t base = (size_t)b * 3072;
    float ir = gi[base + j],         hr = gh[base + j];
    float iz = gi[base + 1024 + j],  hz = gh[base + 1024 + j];
    float in_ = gi[base + 2048 + j], hn = gh[base + 2048 + j];
    float rg = sigmoidf_(ir + hr);
    float zg = sigmoidf_(iz + hz);
    float n = tanhf(in_ + rg * hn);
    float h = hprev[(size_t)b * 1024 + j];
    float hv = (1.f - zg) * n + zg * h;
    belief_out[(size_t)b * 1024 + j] = hv;
    __nv_bfloat16 bh = __float2bfloat16(hv);
    __nv_bfloat16 bl = __float2bfloat16(hv - __bfloat162float(bh));
    sb_belief[base + j] = bh;
    sb_belief[base + 1024 + j] = bl;
    sb_belief[base + 2048 + j] = bh;
    if (j < 6) {
        float pv = pose_t[b * 6 + j];
        __nv_bfloat16 ph = __float2bfloat16(pv);
        __nv_bfloat16 pl = __float2bfloat16(pv - __bfloat162float(ph));
        size_t pb = (size_t)b * 192;
        sb_pose[pb + j] = ph;
        sb_pose[pb + 64 + j] = pl;
        sb_pose[pb + 128 + j] = ph;
    }
}

// ---------------- merged dist heads (sums split-K partials) ------------------
__global__ void dist_head2(const float* __restrict__ ypo, const float* __restrict__ ypo2,
                           const float* __restrict__ ypr, const float* __restrict__ ypr2,
                           const float* __restrict__ pn, const float* __restrict__ rn,
                           float* __restrict__ pm, float* __restrict__ psd, float* __restrict__ ps,
                           float* __restrict__ prm, float* __restrict__ prsd, float* __restrict__ prs,
                           __nv_bfloat16* __restrict__ sb_state)
{
    int i2 = blockIdx.x * 256 + threadIdx.x;
    int half = i2 >> 17;
    int idx = i2 & 131071;
    int b = idx >> 8, c = idx & 255;
    const float* y = half ? ypr : ypo;
    const float* y2 = half ? ypr2 : ypo2;
    const float* nz = half ? rn : pn;
    float m = y[(size_t)b * 512 + c] + y2[(size_t)b * 512 + c];
    float raw = y[(size_t)b * 512 + 256 + c] + y2[(size_t)b * 512 + 256 + c];
    float sd = fmaxf(raw, 0.f) + log1pf(expf(-fabsf(raw))) + 0.1f;
    float st = m + sd * nz[idx];
    if (half) { prm[idx] = m; prsd[idx] = sd; prs[idx] = st; }
    else      { pm[idx] = m;  psd[idx] = sd;  ps[idx] = st; }
    __nv_bfloat16 h = __float2bfloat16(st);
    __nv_bfloat16 l = __float2bfloat16(st - __bfloat162float(h));
    int off = half ? 256 : 0;
    size_t base = (size_t)b * 1536 + off + c;
    sb_state[base] = h;
    sb_state[base + 512] = l;
    sb_state[base + 1024] = h;
}

// ---------------- launch ------------------------------------------------------
extern "C" void kernel_launch(void* const* d_in, const int* in_sizes, int n_in,
                              void* d_out, int out_size)
{
    const float* prev_state   = (const float*)d_in[0];
    const float* prev_belief  = (const float*)d_in[1];
    const float* poses        = (const float*)d_in[2];
    const float* observations = (const float*)d_in[3];
    const float* post_noise   = (const float*)d_in[4];
    const float* prior_noise  = (const float*)d_in[5];
    const float* w_es   = (const float*)d_in[6];
    const float* b_es   = (const float*)d_in[7];
    const float* w_ih   = (const float*)d_in[8];
    const float* w_hh   = (const float*)d_in[9];
    const float* b_ih   = (const float*)d_in[10];
    const float* b_hh   = (const float*)d_in[11];
    const float* w_ebpo = (const float*)d_in[12];
    const float* b_ebpo = (const float*)d_in[13];
    const float* w_spo  = (const float*)d_in[14];
    const float* b_spo  = (const float*)d_in[15];
    const float* w_ebpr = (const float*)d_in[16];
    const float* b_ebpr = (const float*)d_in[17];
    const float* w_spr  = (const float*)d_in[18];
    const float* b_spr  = (const float*)d_in[19];

    float* out = (float*)d_out;
    const size_t SZB = (size_t)TSTEPS * BATCH * BELIEF;
    const size_t SZS = (size_t)TSTEPS * BATCH * STATE;
    float* out_belief = out;
    float* out_prs  = out + SZB;
    float* out_prm  = out + SZB + 1 * SZS;
    float* out_prsd = out + SZB + 2 * SZS;
    float* out_ps   = out + SZB + 3 * SZS;
    float* out_pm   = out + SZB + 4 * SZS;
    float* out_psd  = out + SZB + 5 * SZS;

    float *gi, *gh, *ypo, *ypo2, *ypr, *ypr2;
    cudaGetSymbolAddress((void**)&gi, g_gi);
    cudaGetSymbolAddress((void**)&gh, g_gh);
    cudaGetSymbolAddress((void**)&ypo, g_ypo);
    cudaGetSymbolAddress((void**)&ypo2, g_ypo2);
    cudaGetSymbolAddress((void**)&ypr, g_ypr);
    cudaGetSymbolAddress((void**)&ypr2, g_ypr2);

    __nv_bfloat16 *sb_state, *sb_hidden, *sb_belief, *sb_pose, *sb_hp, *sb_hq, *sb_obs;
    cudaGetSymbolAddress((void**)&sb_state, g_sb_state);
    cudaGetSymbolAddress((void**)&sb_hidden, g_sb_hidden);
    cudaGetSymbolAddress((void**)&sb_belief, g_sb_belief);
    cudaGetSymbolAddress((void**)&sb_pose, g_sb_pose);
    cudaGetSymbolAddress((void**)&sb_hp, g_sb_hp);
    cudaGetSymbolAddress((void**)&sb_hq, g_sb_hq);
    cudaGetSymbolAddress((void**)&sb_obs, g_sb_obs);

    __nv_bfloat16 *wb_es, *wb_ih, *wb_hh, *wb_ebpo, *wb_ebpr, *wb_spo, *wb_spr;
    cudaGetSymbolAddress((void**)&wb_es, g_wb_es);
    cudaGetSymbolAddress((void**)&wb_ih, g_wb_ih);
    cudaGetSymbolAddress((void**)&wb_hh, g_wb_hh);
    cudaGetSymbolAddress((void**)&wb_ebpo, g_wb_ebpo);
    cudaGetSymbolAddress((void**)&wb_ebpr, g_wb_ebpr);
    cudaGetSymbolAddress((void**)&wb_spo, g_wb_spo);
    cudaGetSymbolAddress((void**)&wb_spr, g_wb_spr);

    const int SM64  = NSTAGE * (64 + BN) * ROWB;    // 82944
    const int SM128 = NSTAGE * (128 + BN) * ROWB;   // 110592
    cudaFuncSetAttribute((const void*)gemm_mma<64, true, false, true, false>,
                         cudaFuncAttributeMaxDynamicSharedMemorySize, SM64);
    cudaFuncSetAttribute((const void*)gemm_mma<128, false, true, false, false>,
                         cudaFuncAttributeMaxDynamicSharedMemorySize, SM128);
    cudaFuncSetAttribute((const void*)gemm_mma<64, false, true, false, true>,
                         cudaFuncAttributeMaxDynamicSharedMemorySize, SM64);

    // ---- upfront conversions ----
    dim3 cblk(32, 8);
    convert_w<<<dim3(48, 32), cblk>>>(w_es,   1024, 512,  512,  1536, wb_es);
    convert_w<<<dim3(96, 96), cblk>>>(w_ih,   3072, 1024, 1024, 3072, wb_ih);
    convert_w<<<dim3(96, 96), cblk>>>(w_hh,   3072, 1024, 1024, 3072, wb_hh);
    convert_w<<<dim3(192, 32), cblk>>>(w_ebpo, 1024, 2048, 2048, 6144, wb_ebpo);
    convert_w<<<dim3(102, 32), cblk>>>(w_ebpr, 1024, 1030, 1088, 3264, wb_ebpr);
    convert_w<<<dim3(96, 16), cblk>>>(w_spo,  512,  1024, 1024, 3072, wb_spo);
    convert_w<<<dim3(96, 16), cblk>>>(w_spr,  512,  1024, 1024, 3072, wb_spr);
    split_rows<<<dim3(4, TSTEPS * BATCH), 256>>>(observations, sb_obs, 1024);
    split_rows<<<dim3(4, BATCH), 256>>>(prev_belief, sb_belief, 1024);
    split_state0<<<512, 256>>>(prev_state, sb_state);

    // ---- GEMM params:                A0       A1       Wb       bias    C     C2     Csp       K1    K2    L     Kp    ldc   N
    GemmP pes  = { sb_state,  nullptr, wb_es,   b_es,   nullptr, nullptr, sb_hidden, 512,  0,    512,  1536, 0,    1024 };
    GemmP pgi  = { sb_hidden, nullptr, wb_ih,   b_ih,   gi,      nullptr, nullptr,   1024, 0,    1024, 3072, 3072, 3072 };
    GemmP pgh  = { sb_belief, nullptr, wb_hh,   b_hh,   gh,      nullptr, nullptr,   1024, 0,    1024, 3072, 3072, 3072 };
    GemmP pep  = { sb_belief, nullptr, wb_ebpo, b_ebpo, nullptr, nullptr, sb_hp,     1024, 1024, 2048, 6144, 0,    1024 };
    GemmP peq  = { sb_belief, sb_pose, wb_ebpr, b_ebpr, nullptr, nullptr, sb_hq,     1024, 64,   1088, 3264, 0,    1024 };
    GemmP pso  = { sb_hp,     nullptr, wb_spo,  b_spo,  ypo,     ypo2,    nullptr,   1024, 0,    1024, 3072, 512,  512 };
    GemmP psr  = { sb_hq,     nullptr, wb_spr,  b_spr,  ypr,     ypr2,    nullptr,   1024, 0,    1024, 3072, 512,  512 };

    for (int t = 0; t < TSTEPS; t++) {
        const float* belief_p = (t == 0) ? prev_belief : out_belief + (size_t)(t - 1) * BATCH * BELIEF;
        float* belief_t = out_belief + (size_t)t * BATCH * BELIEF;
        const float* pose_t = poses + (size_t)t * BATCH * 6;
        pep.A1 = sb_obs + (size_t)t * BATCH * 3072;

        gemm_mma<64, true, false, true, false><<<dim3(8, 8, 1), 256, SM64>>>(pes, pes);
        gemm_mma<128, false, true, false, false><<<dim3(24, 4, 2), 256, SM128>>>(pgi, pgh);
        gru_gate<<<2048, 256>>>(gi, gh, belief_p, pose_t, belief_t, sb_belief, sb_pose);
        gemm_mma<64, true, false, true, false><<<dim3(8, 8, 2), 256, SM64>>>(pep, peq);
        gemm_mma<64, false, true, false, true><<<dim3(4, 8, 4), 256, SM64>>>(pso, psr);
        dist_head2<<<1024, 256>>>(ypo, ypo2, ypr, ypr2,
                                  post_noise + (size_t)t * BATCH * STATE,
                                  prior_noise + (size_t)t * BATCH * STATE,
                                  out_pm  + (size_t)t * BATCH * STATE,
                                  out_psd + (size_t)t * BATCH * STATE,
                                  out_ps  + (size_t)t * BATCH * STATE,
                                  out_prm  + (size_t)t * BATCH * STATE,
                                  out_prsd + (size_t)t * BATCH * STATE,
                                  out_prs  + (size_t)t * BATCH * STATE,
                                  sb_state);
    }
}

// round 6
// speedup vs baseline: 4.7887x; 1.3201x over previous
#include <cuda_runtime.h>
#include <cuda_bf16.h>
#include <stdint.h>
#include <math.h>

#define BATCH 512
#define TSTEPS 32
#define BELIEF 1024
#define STATE 256
#define HIDDEN 1024
#define EMB 1024

#define BK 64
#define BN 128
#define APAD 72
#define ROWB (APAD * 2)
#define NSTAGE 3

// ---------------- scratch ----------------------------------------------------
// split-K partial buffers (f32), stacked [split][512, N]
__device__ float g_gi[2 * BATCH * 3 * BELIEF];
__device__ float g_gh[2 * BATCH * 3 * BELIEF];
__device__ float g_hid_p[2 * BATCH * BELIEF];
__device__ float g_hp_p[2 * BATCH * HIDDEN];
__device__ float g_hq_p[2 * BATCH * HIDDEN];
__device__ float g_ypo[4 * BATCH * 2 * STATE];
__device__ float g_ypr[4 * BATCH * 2 * STATE];

// split-bf16 activations: [R, 3L], sections [hi | lo | hi]
__device__ __align__(256) __nv_bfloat16 g_sb_state[BATCH * 3 * 512];
__device__ __align__(256) __nv_bfloat16 g_sb_hidden[BATCH * 3 * 1024];
__device__ __align__(256) __nv_bfloat16 g_sb_belief[BATCH * 3 * 1024];
__device__ __align__(256) __nv_bfloat16 g_sb_pose[BATCH * 3 * 64];
__device__ __align__(256) __nv_bfloat16 g_sb_hp[BATCH * 3 * 1024];
__device__ __align__(256) __nv_bfloat16 g_sb_hq[BATCH * 3 * 1024];
__device__ __align__(256) __nv_bfloat16 g_sb_obs[(size_t)TSTEPS * BATCH * 3 * 1024];

// split-bf16 weights [N, Kp=3L], sections [hi | hi | lo]
__device__ __align__(256) __nv_bfloat16 g_wb_es[1024 * 1536];
__device__ __align__(256) __nv_bfloat16 g_wb_ih[3072 * 3072];
__device__ __align__(256) __nv_bfloat16 g_wb_hh[3072 * 3072];
__device__ __align__(256) __nv_bfloat16 g_wb_ebpo[1024 * 6144];
__device__ __align__(256) __nv_bfloat16 g_wb_ebpr[1024 * 3264];
__device__ __align__(256) __nv_bfloat16 g_wb_spo[512 * 3072];
__device__ __align__(256) __nv_bfloat16 g_wb_spr[512 * 3072];

// ---------------- helpers ----------------------------------------------------
__device__ __forceinline__ uint32_t smem_u32(const void* p) {
    uint32_t a;
    asm("{ .reg .u64 t; cvta.to.shared.u64 t, %1; cvt.u32.u64 %0, t; }" : "=r"(a) : "l"(p));
    return a;
}
__device__ __forceinline__ void mma_bf16(float* c, const uint32_t* a, uint32_t b0, uint32_t b1) {
    asm volatile("mma.sync.aligned.m16n8k16.row.col.f32.bf16.bf16.f32 "
        "{%0,%1,%2,%3}, {%4,%5,%6,%7}, {%8,%9}, {%0,%1,%2,%3};"
        : "+f"(c[0]), "+f"(c[1]), "+f"(c[2]), "+f"(c[3])
        : "r"(a[0]), "r"(a[1]), "r"(a[2]), "r"(a[3]), "r"(b0), "r"(b1));
}

struct GemmP {
    const __nv_bfloat16* A0;
    const __nv_bfloat16* A1;
    const __nv_bfloat16* Wb;
    const float* bias;
    float* C;                       // partial base; split s writes C + s*partStride
    int K1, K2, L, Kp, ldc, partStride;
};

// ---------------- tensor-core GEMM (pure f32-partial, split-K') --------------
// blockIdx.z = gemm_idx * SPLITS + split_idx
template <int BMT, int SPLITS>
__global__ __launch_bounds__(256, 2) void gemm_mma(GemmP p0, GemmP p1)
{
    constexpr int MF = BMT / 64;
    constexpr int ASZ = BMT * ROWB;
    constexpr int BSZ = BN * ROWB;
    extern __shared__ char smem[];
    const int z = blockIdx.z;
    const int gidx = z / SPLITS, sidx = z % SPLITS;
    const GemmP p = gidx ? p1 : p0;
    const int nkt_all = p.Kp / BK;
    const int nbase = nkt_all / SPLITS, nrem = nkt_all % SPLITS;
    const int nkt = nbase + (sidx < nrem);
    const int kb = sidx * nbase + min(sidx, nrem);
    float* Cout = p.C + (size_t)sidx * p.partStride;
    const bool addBias = (sidx == 0);

    const int tid = threadIdx.x;
    const int wid = tid >> 5, lane = tid & 31;
    const int row0 = blockIdx.y * BMT, col0 = blockIdx.x * BN;
    const uint32_t sbase = smem_u32(smem);

    auto issue = [&](int i, int slot) {
        const int kp = i * BK;
        const int sec = (kp >= p.L) + (kp >= 2 * p.L);
        const int rb = kp - sec * p.L;
        const bool useA0 = (rb < p.K1);
        const __nv_bfloat16* abase = useA0
            ? (p.A0 + (size_t)row0 * (3 * p.K1) + sec * p.K1 + rb)
            : (p.A1 + (size_t)row0 * (3 * p.K2) + sec * p.K2 + (rb - p.K1));
        const int astr = useA0 ? 3 * p.K1 : 3 * p.K2;
        const uint32_t da = sbase + slot * ASZ;
        #pragma unroll
        for (int q = 0; q < BMT * 8 / 256; q++) {
            int idx = tid + q * 256;
            int r = idx >> 3, c = idx & 7;
            asm volatile("cp.async.cg.shared.global [%0], [%1], 16;"
                :: "r"(da + r * ROWB + c * 16), "l"(abase + (size_t)r * astr + c * 8));
        }
        const __nv_bfloat16* bbase = p.Wb + (size_t)col0 * p.Kp + i * BK;
        const uint32_t db = sbase + NSTAGE * ASZ + slot * BSZ;
        #pragma unroll
        for (int q = 0; q < BN * 8 / 256; q++) {
            int idx = tid + q * 256;
            int r = idx >> 3, c = idx & 7;
            asm volatile("cp.async.cg.shared.global [%0], [%1], 16;"
                :: "r"(db + r * ROWB + c * 16), "l"(bbase + (size_t)r * p.Kp + c * 8));
        }
        asm volatile("cp.async.commit_group;" ::: "memory");
    };

    const int wm = wid & 3, wn = wid >> 2;
    const uint32_t lrow = lane & 15;
    const uint32_t lk16 = (lane >> 4) * 16;

    float acc[MF][8][4];
    #pragma unroll
    for (int mf = 0; mf < MF; mf++)
        #pragma unroll
        for (int j = 0; j < 8; j++)
            #pragma unroll
            for (int q = 0; q < 4; q++) acc[mf][j][q] = 0.f;

    issue(kb + 0, 0);
    issue(kb + 1, 1);

    for (int it = 0; it < nkt; it++) {
        asm volatile("cp.async.wait_group 1;" ::: "memory");
        __syncthreads();
        const int slot = it % NSTAGE;
        const uint32_t aS = sbase + slot * ASZ + (wm * 16 * MF + lrow) * ROWB + lk16;
        const uint32_t bS = sbase + NSTAGE * ASZ + slot * BSZ + (wn * 64 + lrow) * ROWB + lk16;
        #pragma unroll
        for (int ks = 0; ks < 4; ks++) {
            uint32_t a[MF][4];
            #pragma unroll
            for (int mf = 0; mf < MF; mf++)
                asm volatile("ldmatrix.sync.aligned.m8n8.x4.shared.b16 {%0,%1,%2,%3}, [%4];"
                    : "=r"(a[mf][0]), "=r"(a[mf][1]), "=r"(a[mf][2]), "=r"(a[mf][3])
                    : "r"(aS + mf * 16 * ROWB + ks * 32));
            #pragma unroll
            for (int nb = 0; nb < 4; nb++) {
                uint32_t b[4];
                asm volatile("ldmatrix.sync.aligned.m8n8.x4.shared.b16 {%0,%1,%2,%3}, [%4];"
                    : "=r"(b[0]), "=r"(b[1]), "=r"(b[2]), "=r"(b[3])
                    : "r"(bS + nb * 16 * ROWB + ks * 32));
                #pragma unroll
                for (int mf = 0; mf < MF; mf++) {
                    mma_bf16(acc[mf][2 * nb + 0], a[mf], b[0], b[2]);
                    mma_bf16(acc[mf][2 * nb + 1], a[mf], b[1], b[3]);
                }
            }
        }
        if (it + 2 < nkt) issue(kb + it + 2, (it + 2) % NSTAGE);
        else asm volatile("cp.async.commit_group;" ::: "memory");
    }

    #pragma unroll
    for (int mf = 0; mf < MF; mf++) {
        #pragma unroll
        for (int nf = 0; nf < 8; nf++) {
            const int row_ = row0 + wm * 16 * MF + mf * 16 + (lane >> 2);
            const int col_ = col0 + wn * 64 + nf * 8 + (lane & 3) * 2;
            const float b0 = addBias ? p.bias[col_] : 0.f;
            const float b1 = addBias ? p.bias[col_ + 1] : 0.f;
            #pragma unroll
            for (int rh = 0; rh < 2; rh++) {
                float v0 = acc[mf][nf][rh * 2 + 0] + b0;
                float v1 = acc[mf][nf][rh * 2 + 1] + b1;
                const int rr = row_ + rh * 8;
                *reinterpret_cast<float2*>(&Cout[(size_t)rr * p.ldc + col_]) = make_float2(v0, v1);
            }
        }
    }
}

// ---------------- weight conversion -----------------------------------------
__global__ void convert_w(const float* __restrict__ W, int N, int Keff, int L,
                          int Kp, __nv_bfloat16* __restrict__ out)
{
    __shared__ unsigned short tile[32][33];
    int k0 = blockIdx.x * 32, n0 = blockIdx.y * 32;
    int tx = threadIdx.x, ty = threadIdx.y;
    #pragma unroll
    for (int q = 0; q < 4; q++) {
        int kl = ty + q * 8;
        int kp = k0 + kl;
        int s = kp / L;
        int rr = kp - s * L;
        float v = (rr < Keff) ? W[(size_t)rr * N + n0 + tx] : 0.f;
        __nv_bfloat16 b;
        if (s == 2) {
            __nv_bfloat16 h = __float2bfloat16(v);
            b = __float2bfloat16(v - __bfloat162float(h));
        } else b = __float2bfloat16(v);
        tile[kl][tx] = __bfloat16_as_ushort(b);
    }
    __syncthreads();
    #pragma unroll
    for (int q = 0; q < 4; q++) {
        int nl = ty + q * 8;
        reinterpret_cast<unsigned short*>(out)[(size_t)(n0 + nl) * Kp + k0 + tx] = tile[tx][nl];
    }
}

// ---------------- activation splits ------------------------------------------
__global__ void split_rows(const float* __restrict__ src, __nv_bfloat16* __restrict__ dst, int L)
{
    int r = blockIdx.y;
    int c = blockIdx.x * 256 + threadIdx.x;
    float v = src[(size_t)r * L + c];
    __nv_bfloat16 h = __float2bfloat16(v);
    __nv_bfloat16 l = __float2bfloat16(v - __bfloat162float(h));
    size_t o = (size_t)r * 3 * L + c;
    dst[o] = h; dst[o + L] = l; dst[o + 2 * L] = h;
}
__global__ void split_state0(const float* __restrict__ ps, __nv_bfloat16* __restrict__ dst)
{
    int idx = blockIdx.x * 256 + threadIdx.x;
    int b = idx >> 8, c = idx & 255;
    float v = ps[idx];
    __nv_bfloat16 h = __float2bfloat16(v);
    __nv_bfloat16 l = __float2bfloat16(v - __bfloat162float(h));
    size_t base = (size_t)b * 1536;
    dst[base + c] = h;        dst[base + 256 + c] = h;
    dst[base + 512 + c] = l;  dst[base + 768 + c] = l;
    dst[base + 1024 + c] = h; dst[base + 1280 + c] = h;
}

// ---------------- reduce + relu + split --------------------------------------
// one tensor: partials [2][512,1024] -> sb [512, 3*1024]
__global__ void rrs1(const float* __restrict__ part, __nv_bfloat16* __restrict__ dst)
{
    int idx = blockIdx.x * 256 + threadIdx.x;          // 512*1024
    int r = idx >> 10, c = idx & 1023;
    float v = part[idx] + part[idx + 512 * 1024];
    v = fmaxf(v, 0.f);
    __nv_bfloat16 h = __float2bfloat16(v);
    __nv_bfloat16 l = __float2bfloat16(v - __bfloat162float(h));
    size_t o = (size_t)r * 3072 + c;
    dst[o] = h; dst[o + 1024] = l; dst[o + 2048] = h;
}
// two tensors (hp, hq)
__global__ void rrs2(const float* __restrict__ pa, const float* __restrict__ pb,
                     __nv_bfloat16* __restrict__ da, __nv_bfloat16* __restrict__ db)
{
    int i2 = blockIdx.x * 256 + threadIdx.x;           // 2*512*1024
    int half = i2 >> 19;
    int idx = i2 & 524287;
    const float* part = half ? pb : pa;
    __nv_bfloat16* dst = half ? db : da;
    int r = idx >> 10, c = idx & 1023;
    float v = part[idx] + part[idx + 512 * 1024];
    v = fmaxf(v, 0.f);
    __nv_bfloat16 h = __float2bfloat16(v);
    __nv_bfloat16 l = __float2bfloat16(v - __bfloat162float(h));
    size_t o = (size_t)r * 3072 + c;
    dst[o] = h; dst[o + 1024] = l; dst[o + 2048] = h;
}

// ---------------- GRU gate (sums split-K partials) ---------------------------
__device__ __forceinline__ float sigmoidf_(float x) { return 1.f / (1.f + expf(-x)); }
#define PS3 (512 * 3072)

__global__ void gru_gate(const float* __restrict__ gi, const float* __restrict__ gh,
                         const float* __restrict__ hprev, const float* __restrict__ pose_t,
                         float* __restrict__ belief_out,
                         __nv_bfloat16* __restrict__ sb_belief,
                         __nv_bfloat16* __restrict__ sb_pose)
{
    int idx = blockIdx.x * blockDim.x + threadIdx.x;
    int b = idx >> 10;
    int j = idx & 1023;
    size_t base = (size_t)b * 3072;
    float ir = gi[base + j] + gi[PS3 + base + j];
    float hr = gh[base + j] + gh[PS3 + base + j];
    float iz = gi[base + 1024 + j] + gi[PS3 + base + 1024 + j];
    float hz = gh[base + 1024 + j] + gh[PS3 + base + 1024 + j];
    float in_ = gi[base + 2048 + j] + gi[PS3 + base + 2048 + j];
    float hn = gh[base + 2048 + j] + gh[PS3 + base + 2048 + j];
    float rg = sigmoidf_(ir + hr);
    float zg = sigmoidf_(iz + hz);
    float n = tanhf(in_ + rg * hn);
    float h = hprev[(size_t)b * 1024 + j];
    float hv = (1.f - zg) * n + zg * h;
    belief_out[(size_t)b * 1024 + j] = hv;
    __nv_bfloat16 bh = __float2bfloat16(hv);
    __nv_bfloat16 bl = __float2bfloat16(hv - __bfloat162float(bh));
    sb_belief[base + j] = bh;
    sb_belief[base + 1024 + j] = bl;
    sb_belief[base + 2048 + j] = bh;
    if (j < 6) {
        float pv = pose_t[b * 6 + j];
        __nv_bfloat16 ph = __float2bfloat16(pv);
        __nv_bfloat16 pl = __float2bfloat16(pv - __bfloat162float(ph));
        size_t pb = (size_t)b * 192;
        sb_pose[pb + j] = ph;
        sb_pose[pb + 64 + j] = pl;
        sb_pose[pb + 128 + j] = ph;
    }
}

// ---------------- merged dist heads (sums 4 split-K partials) ----------------
#define PSH (512 * 512)
__global__ void dist_head2(const float* __restrict__ ypo, const float* __restrict__ ypr,
                           const float* __restrict__ pn, const float* __restrict__ rn,
                           float* __restrict__ pm, float* __restrict__ psd, float* __restrict__ ps,
                           float* __restrict__ prm, float* __restrict__ prsd, float* __restrict__ prs,
                           __nv_bfloat16* __restrict__ sb_state)
{
    int i2 = blockIdx.x * 256 + threadIdx.x;
    int half = i2 >> 17;
    int idx = i2 & 131071;
    int b = idx >> 8, c = idx & 255;
    const float* y = half ? ypr : ypo;
    const float* nz = half ? rn : pn;
    size_t bm = (size_t)b * 512 + c;
    size_t br = bm + 256;
    float m = y[bm] + y[PSH + bm] + y[2 * PSH + bm] + y[3 * PSH + bm];
    float raw = y[br] + y[PSH + br] + y[2 * PSH + br] + y[3 * PSH + br];
    float sd = fmaxf(raw, 0.f) + log1pf(expf(-fabsf(raw))) + 0.1f;
    float st = m + sd * nz[idx];
    if (half) { prm[idx] = m; prsd[idx] = sd; prs[idx] = st; }
    else      { pm[idx] = m;  psd[idx] = sd;  ps[idx] = st; }
    __nv_bfloat16 h = __float2bfloat16(st);
    __nv_bfloat16 l = __float2bfloat16(st - __bfloat162float(h));
    int off = half ? 256 : 0;
    size_t base = (size_t)b * 1536 + off + c;
    sb_state[base] = h;
    sb_state[base + 512] = l;
    sb_state[base + 1024] = h;
}

// ---------------- launch ------------------------------------------------------
extern "C" void kernel_launch(void* const* d_in, const int* in_sizes, int n_in,
                              void* d_out, int out_size)
{
    const float* prev_state   = (const float*)d_in[0];
    const float* prev_belief  = (const float*)d_in[1];
    const float* poses        = (const float*)d_in[2];
    const float* observations = (const float*)d_in[3];
    const float* post_noise   = (const float*)d_in[4];
    const float* prior_noise  = (const float*)d_in[5];
    const float* w_es   = (const float*)d_in[6];
    const float* b_es   = (const float*)d_in[7];
    const float* w_ih   = (const float*)d_in[8];
    const float* w_hh   = (const float*)d_in[9];
    const float* b_ih   = (const float*)d_in[10];
    const float* b_hh   = (const float*)d_in[11];
    const float* w_ebpo = (const float*)d_in[12];
    const float* b_ebpo = (const float*)d_in[13];
    const float* w_spo  = (const float*)d_in[14];
    const float* b_spo  = (const float*)d_in[15];
    const float* w_ebpr = (const float*)d_in[16];
    const float* b_ebpr = (const float*)d_in[17];
    const float* w_spr  = (const float*)d_in[18];
    const float* b_spr  = (const float*)d_in[19];

    float* out = (float*)d_out;
    const size_t SZB = (size_t)TSTEPS * BATCH * BELIEF;
    const size_t SZS = (size_t)TSTEPS * BATCH * STATE;
    float* out_belief = out;
    float* out_prs  = out + SZB;
    float* out_prm  = out + SZB + 1 * SZS;
    float* out_prsd = out + SZB + 2 * SZS;
    float* out_ps   = out + SZB + 3 * SZS;
    float* out_pm   = out + SZB + 4 * SZS;
    float* out_psd  = out + SZB + 5 * SZS;

    float *gi, *gh, *hid_p, *hp_p, *hq_p, *ypo, *ypr;
    cudaGetSymbolAddress((void**)&gi, g_gi);
    cudaGetSymbolAddress((void**)&gh, g_gh);
    cudaGetSymbolAddress((void**)&hid_p, g_hid_p);
    cudaGetSymbolAddress((void**)&hp_p, g_hp_p);
    cudaGetSymbolAddress((void**)&hq_p, g_hq_p);
    cudaGetSymbolAddress((void**)&ypo, g_ypo);
    cudaGetSymbolAddress((void**)&ypr, g_ypr);

    __nv_bfloat16 *sb_state, *sb_hidden, *sb_belief, *sb_pose, *sb_hp, *sb_hq, *sb_obs;
    cudaGetSymbolAddress((void**)&sb_state, g_sb_state);
    cudaGetSymbolAddress((void**)&sb_hidden, g_sb_hidden);
    cudaGetSymbolAddress((void**)&sb_belief, g_sb_belief);
    cudaGetSymbolAddress((void**)&sb_pose, g_sb_pose);
    cudaGetSymbolAddress((void**)&sb_hp, g_sb_hp);
    cudaGetSymbolAddress((void**)&sb_hq, g_sb_hq);
    cudaGetSymbolAddress((void**)&sb_obs, g_sb_obs);

    __nv_bfloat16 *wb_es, *wb_ih, *wb_hh, *wb_ebpo, *wb_ebpr, *wb_spo, *wb_spr;
    cudaGetSymbolAddress((void**)&wb_es, g_wb_es);
    cudaGetSymbolAddress((void**)&wb_ih, g_wb_ih);
    cudaGetSymbolAddress((void**)&wb_hh, g_wb_hh);
    cudaGetSymbolAddress((void**)&wb_ebpo, g_wb_ebpo);
    cudaGetSymbolAddress((void**)&wb_ebpr, g_wb_ebpr);
    cudaGetSymbolAddress((void**)&wb_spo, g_wb_spo);
    cudaGetSymbolAddress((void**)&wb_spr, g_wb_spr);

    const int SM64  = NSTAGE * (64 + BN) * ROWB;    // 82944
    const int SM128 = NSTAGE * (128 + BN) * ROWB;   // 110592
    cudaFuncSetAttribute((const void*)gemm_mma<64, 2>,
                         cudaFuncAttributeMaxDynamicSharedMemorySize, SM64);
    cudaFuncSetAttribute((const void*)gemm_mma<128, 2>,
                         cudaFuncAttributeMaxDynamicSharedMemorySize, SM128);
    cudaFuncSetAttribute((const void*)gemm_mma<64, 4>,
                         cudaFuncAttributeMaxDynamicSharedMemorySize, SM64);

    // ---- upfront conversions ----
    dim3 cblk(32, 8);
    convert_w<<<dim3(48, 32), cblk>>>(w_es,   1024, 512,  512,  1536, wb_es);
    convert_w<<<dim3(96, 96), cblk>>>(w_ih,   3072, 1024, 1024, 3072, wb_ih);
    convert_w<<<dim3(96, 96), cblk>>>(w_hh,   3072, 1024, 1024, 3072, wb_hh);
    convert_w<<<dim3(192, 32), cblk>>>(w_ebpo, 1024, 2048, 2048, 6144, wb_ebpo);
    convert_w<<<dim3(102, 32), cblk>>>(w_ebpr, 1024, 1030, 1088, 3264, wb_ebpr);
    convert_w<<<dim3(96, 16), cblk>>>(w_spo,  512,  1024, 1024, 3072, wb_spo);
    convert_w<<<dim3(96, 16), cblk>>>(w_spr,  512,  1024, 1024, 3072, wb_spr);
    split_rows<<<dim3(4, TSTEPS * BATCH), 256>>>(observations, sb_obs, 1024);
    split_rows<<<dim3(4, BATCH), 256>>>(prev_belief, sb_belief, 1024);
    split_state0<<<512, 256>>>(prev_state, sb_state);

    // ---- GEMM params:               A0        A1        Wb       bias    C      K1    K2    L     Kp    ldc   partStride
    GemmP pes  = { sb_state,  nullptr, wb_es,   b_es,   hid_p, 512,  0,    512,  1536, 1024, 512 * 1024 };
    GemmP pgi  = { sb_hidden, nullptr, wb_ih,   b_ih,   gi,    1024, 0,    1024, 3072, 3072, 512 * 3072 };
    GemmP pgh  = { sb_belief, nullptr, wb_hh,   b_hh,   gh,    1024, 0,    1024, 3072, 3072, 512 * 3072 };
    GemmP pep  = { sb_belief, nullptr, wb_ebpo, b_ebpo, hp_p,  1024, 1024, 2048, 6144, 1024, 512 * 1024 };
    GemmP peq  = { sb_belief, sb_pose, wb_ebpr, b_ebpr, hq_p,  1024, 64,   1088, 3264, 1024, 512 * 1024 };
    GemmP pso  = { sb_hp,     nullptr, wb_spo,  b_spo,  ypo,   1024, 0,    1024, 3072, 512,  512 * 512 };
    GemmP psr  = { sb_hq,     nullptr, wb_spr,  b_spr,  ypr,   1024, 0,    1024, 3072, 512,  512 * 512 };

    for (int t = 0; t < TSTEPS; t++) {
        const float* belief_p = (t == 0) ? prev_belief : out_belief + (size_t)(t - 1) * BATCH * BELIEF;
        float* belief_t = out_belief + (size_t)t * BATCH * BELIEF;
        const float* pose_t = poses + (size_t)t * BATCH * 6;
        pep.A1 = sb_obs + (size_t)t * BATCH * 3072;

        gemm_mma<64, 2><<<dim3(8, 8, 2), 256, SM64>>>(pes, pes);
        rrs1<<<2048, 256>>>(hid_p, sb_hidden);
        gemm_mma<128, 2><<<dim3(24, 4, 4), 256, SM128>>>(pgi, pgh);
        gru_gate<<<2048, 256>>>(gi, gh, belief_p, pose_t, belief_t, sb_belief, sb_pose);
        gemm_mma<64, 2><<<dim3(8, 8, 4), 256, SM64>>>(pep, peq);
        rrs2<<<4096, 256>>>(hp_p, hq_p, sb_hp, sb_hq);
        gemm_mma<64, 4><<<dim3(4, 8, 8), 256, SM64>>>(pso, psr);
        dist_head2<<<1024, 256>>>(ypo, ypr,
                                  post_noise + (size_t)t * BATCH * STATE,
                                  prior_noise + (size_t)t * BATCH * STATE,
                                  out_pm  + (size_t)t * BATCH * STATE,
                                  out_psd + (size_t)t * BATCH * STATE,
                                  out_ps  + (size_t)t * BATCH * STATE,
                                  out_prm  + (size_t)t * BATCH * STATE,
                                  out_prsd + (size_t)t * BATCH * STATE,
                                  out_prs  + (size_t)t * BATCH * STATE,
                                  sb_state);
    }
}